// round 12
// baseline (speedup 1.0000x reference)
#include <cuda_runtime.h>
#include <cuda_fp16.h>
#include <cstdint>

#define S_LEN 4096
#define D_MODEL 1024
#define NH 16
#define DKH 64
#define DKV 256
#define EXP_SCALE 0.1803368801111244f   // 0.125 * log2(e)

// ===========================================================================
// Scratch (__device__ globals; no allocation allowed)
// ===========================================================================
__device__ __half g_xh[S_LEN * D_MODEL];
__device__ __half g_Wqt[D_MODEL * D_MODEL];
__device__ __half g_Wkt[DKV * D_MODEL];
__device__ __half g_Wvt[DKV * D_MODEL];
__device__ __half g_Wot[D_MODEL * D_MODEL];
__device__ __half g_Qh[S_LEN * D_MODEL];
__device__ __half g_Kh[S_LEN * DKV];
__device__ __half g_Vh[S_LEN * DKV];
__device__ __half g_AOh[S_LEN * D_MODEL];

// ===========================================================================
// Low-level helpers (sm_80-era instructions: valid on base sm_103 target)
// ===========================================================================
__device__ __forceinline__ uint32_t smem_u32(const void* p) {
    uint32_t a;
    asm("{ .reg .u64 t; cvta.to.shared.u64 t, %1; cvt.u32.u64 %0, t; }" : "=r"(a) : "l"(p));
    return a;
}
#define SWZ(off) ((off) ^ (((off) >> 3) & 0x70))

__device__ __forceinline__ void cp16(uint32_t dst, const void* src) {
    asm volatile("cp.async.cg.shared.global [%0], [%1], 16;" :: "r"(dst), "l"(src));
}
#define CP_COMMIT() asm volatile("cp.async.commit_group;" ::: "memory")
#define CP_WAIT0()  asm volatile("cp.async.wait_group 0;" ::: "memory")

__device__ __forceinline__ void ldsm_x4(uint32_t* r, uint32_t addr) {
    asm volatile("ldmatrix.sync.aligned.m8n8.x4.shared.b16 {%0,%1,%2,%3}, [%4];"
        : "=r"(r[0]), "=r"(r[1]), "=r"(r[2]), "=r"(r[3]) : "r"(addr));
}
__device__ __forceinline__ void ldsm_x4_t(uint32_t* r, uint32_t addr) {
    asm volatile("ldmatrix.sync.aligned.m8n8.x4.trans.shared.b16 {%0,%1,%2,%3}, [%4];"
        : "=r"(r[0]), "=r"(r[1]), "=r"(r[2]), "=r"(r[3]) : "r"(addr));
}
__device__ __forceinline__ void mma16816(float* d, const uint32_t* a, const uint32_t* b) {
    asm volatile(
        "mma.sync.aligned.m16n8k16.row.col.f32.f16.f16.f32 "
        "{%0,%1,%2,%3}, {%4,%5,%6,%7}, {%8,%9}, {%0,%1,%2,%3};"
        : "+f"(d[0]), "+f"(d[1]), "+f"(d[2]), "+f"(d[3])
        : "r"(a[0]), "r"(a[1]), "r"(a[2]), "r"(a[3]), "r"(b[0]), "r"(b[1]));
}

// FMA-pipe exp (no MUFU): p = exp(s * 0.125) * mval. Poly in log2-domain.
__device__ __forceinline__ float fexp(float s, float mval) {
    float y = s * EXP_SCALE;
    float t = y + 12582912.0f;               // 1.5*2^23 magic round
    int   ni = __float_as_int(t) - 0x4B400000;
    float f = y - (t - 12582912.0f);         // [-0.5, 0.5]
    float p = fmaf(f, 0.0096181291f, 0.0555041087f);
    p = fmaf(p, f, 0.2402265069f);
    p = fmaf(p, f, 0.6931471806f);
    p = fmaf(p, f, 1.0f);                    // 2^f, err ~4e-5
    p = __int_as_float(__float_as_int(p) + (ni << 23));
    return p * mval;
}

__device__ __forceinline__ uint32_t packh2(float a, float b) {
    __half2 h = __floats2half2_rn(a, b);
    return *reinterpret_cast<uint32_t*>(&h);
}

// ===========================================================================
// Prep kernels
// ===========================================================================
__global__ void tofp16_kernel(const float* __restrict__ in, __half* __restrict__ out, int n4) {
    int i = blockIdx.x * blockDim.x + threadIdx.x;
    if (i < n4) {
        float4 v = reinterpret_cast<const float4*>(in)[i];
        uint2 H;
        H.x = packh2(v.x, v.y);
        H.y = packh2(v.z, v.w);
        reinterpret_cast<uint2*>(out)[i] = H;
    }
}

// All four W[K,N] -> Wt[N,K] fp16 transposes in ONE launch.
__global__ void prep_weights_kernel(const float* __restrict__ Wq, const float* __restrict__ Wk,
                                    const float* __restrict__ Wv, const float* __restrict__ Wo)
{
    __shared__ float t[32][33];
    int b = blockIdx.x;
    const float* W; __half* Wt; int N;
    if (b < 1024)      { W = Wq; Wt = g_Wqt; N = 1024; }
    else if (b < 1280) { W = Wk; Wt = g_Wkt; N = 256;  b -= 1024; }
    else if (b < 1536) { W = Wv; Wt = g_Wvt; N = 256;  b -= 1280; }
    else               { W = Wo; Wt = g_Wot; N = 1024; b -= 1536; }
    const int K = 1024;
    const int nb = N / 32;
    int n0 = (b % nb) * 32, k0 = (b / nb) * 32;
    int tx = threadIdx.x, ty = threadIdx.y;
#pragma unroll
    for (int j = 0; j < 32; j += 8)
        t[ty + j][tx] = W[(long)(k0 + ty + j) * N + n0 + tx];
    __syncthreads();
#pragma unroll
    for (int j = 0; j < 32; j += 8)
        Wt[(long)(n0 + ty + j) * K + k0 + tx] = __float2half_rn(t[tx][ty + j]);
}

// ===========================================================================
// Shared single-pass HMMA GEMM body: C[bm:+128, bn:+128] = A @ Bt^T + bias
// 256 thr, tile 128x128, K-chunk 64, cp.async double-buffered (2x32KB).
// ===========================================================================
#define GSTAGE 32768
#define GSMEM (2 * GSTAGE)   // 64 KB -> 2 CTAs/SM with <=128 regs

__device__ __forceinline__ void gemm_body(
    const __half* __restrict__ Ah, const __half* __restrict__ Bh,
    const float* __restrict__ bias, float* Cf, __half* Ch,
    int Kdim, int Nout, int bm, int bn, char* sm)
{
    uint32_t sb = smem_u32(sm);
    const int tid = threadIdx.x, lane = tid & 31, wid = tid >> 5;
    const int wm = (wid >> 2) * 64, wn = (wid & 3) * 32;

    float acc[4][4][4];
#pragma unroll
    for (int a = 0; a < 4; a++)
#pragma unroll
        for (int b = 0; b < 4; b++)
#pragma unroll
            for (int c = 0; c < 4; c++) acc[a][b][c] = 0.f;

    auto load_stage = [&](int st, int k0) {
        uint32_t base = sb + st * GSTAGE;
#pragma unroll
        for (int i = 0; i < 8; i++) {
            int c = i * 256 + tid;            // 0..2047
            int tsr = c >> 10;                // 0:A 1:B
            int idx = c & 1023;
            int row = idx >> 3, ch = idx & 7;
            const __half* src = (tsr == 0)
                ? Ah + (long)(bm + row) * Kdim + k0 + ch * 8
                : Bh + (long)(bn + row) * Kdim + k0 + ch * 8;
            cp16(base + tsr * 16384 + SWZ(row * 128 + ch * 16), src);
        }
    };

    const int nk = Kdim / 64;
    load_stage(0, 0);
    CP_COMMIT();

    const int r8 = lane & 7, grp = lane >> 3;

    for (int kc = 0; kc < nk; kc++) {
        CP_WAIT0();
        __syncthreads();
        if (kc + 1 < nk) load_stage((kc + 1) & 1, (kc + 1) * 64);
        CP_COMMIT();

        uint32_t base = sb + (kc & 1) * GSTAGE;
        uint32_t aH = base, bH = base + 16384;

#pragma unroll
        for (int s = 0; s < 4; s++) {
            uint32_t ah[4][4], bh[2][4];
            int arow = wm + ((grp & 1) ? 8 : 0) + r8;
            int ach = 2 * s + (grp >> 1);
#pragma unroll
            for (int mt = 0; mt < 4; mt++)
                ldsm_x4(ah[mt], aH + SWZ((arow + mt * 16) * 128 + ach * 16));
            int broff = ((grp >= 2) ? 8 : 0) + r8;
            int bch = 2 * s + (grp & 1);
#pragma unroll
            for (int t = 0; t < 2; t++)
                ldsm_x4(bh[t], bH + SWZ((wn + t * 16 + broff) * 128 + bch * 16));
#pragma unroll
            for (int mt = 0; mt < 4; mt++)
#pragma unroll
                for (int nt = 0; nt < 4; nt++)
                    mma16816(acc[mt][nt], ah[mt], &bh[nt >> 1][(nt & 1) * 2]);
        }
        __syncthreads();
    }

    // epilogue
    const int r = lane >> 2, cq = (lane & 3) * 2;
#pragma unroll
    for (int mt = 0; mt < 4; mt++)
#pragma unroll
        for (int nt = 0; nt < 4; nt++) {
            int col = bn + wn + nt * 8 + cq;
            float b0 = bias[col], b1 = bias[col + 1];
            long row0 = bm + wm + mt * 16 + r;
            float v0 = acc[mt][nt][0] + b0, v1 = acc[mt][nt][1] + b1;
            float v2 = acc[mt][nt][2] + b0, v3 = acc[mt][nt][3] + b1;
            if (Cf) {
                *reinterpret_cast<float2*>(Cf + row0 * Nout + col) = make_float2(v0, v1);
                *reinterpret_cast<float2*>(Cf + (row0 + 8) * Nout + col) = make_float2(v2, v3);
            } else {
                *reinterpret_cast<uint32_t*>(Ch + row0 * Nout + col) = packh2(v0, v1);
                *reinterpret_cast<uint32_t*>(Ch + (row0 + 8) * Nout + col) = packh2(v2, v3);
            }
        }
}

// Fused QKV projection: grid (12, 32). bx 0-7: Q, 8-9: K, 10-11: V.
__global__ __launch_bounds__(256, 2) void qkv_gemm(
    const __half* __restrict__ xh,
    const float* __restrict__ bq, const float* __restrict__ bk,
    const float* __restrict__ bv)
{
    extern __shared__ char sm[];
    int bx = blockIdx.x, bm = blockIdx.y * 128;
    const __half* B; const float* bias; __half* out; int Nout; int bn;
    if (bx < 8)       { B = g_Wqt; bias = bq; out = g_Qh; Nout = 1024; bn = bx * 128; }
    else if (bx < 10) { B = g_Wkt; bias = bk; out = g_Kh; Nout = 256;  bn = (bx - 8) * 128; }
    else              { B = g_Wvt; bias = bv; out = g_Vh; Nout = 256;  bn = (bx - 10) * 128; }
    gemm_body(xh, B, bias, nullptr, out, D_MODEL, Nout, bm, bn, sm);
}

// Output projection: grid (8, 32), fp32 out.
__global__ __launch_bounds__(256, 2) void o_gemm(
    const __half* __restrict__ aoh, const float* __restrict__ bo,
    float* __restrict__ out)
{
    extern __shared__ char sm[];
    gemm_body(aoh, g_Wot, bo, out, nullptr, D_MODEL, D_MODEL,
              blockIdx.y * 128, blockIdx.x * 128, sm);
}

// ===========================================================================
// HMMA flash attention: 256 thr (8 warps x 16 q-rows), BQ=128, BKV=64, DK=64.
// Restructured for 2 CTAs/SM: the 64-kv tile is processed as two independent
// 32-kv halves (S -> exp -> P -> PV per half) so live regs drop ~144 -> ~112.
// ===========================================================================
#define ASTAGE 16640
#define AMASKO 16384
#define ASMEM  (2 * ASTAGE)

__global__ __launch_bounds__(256, 2) void attn_tc_kernel(
    const __half* __restrict__ Qh,
    const __half* __restrict__ Kh,
    const __half* __restrict__ Vh,
    const int* __restrict__ maskG,
    __half* __restrict__ AOh)
{
    extern __shared__ char sm[];
    uint32_t sb = smem_u32(sm);
    const int tid = threadIdx.x, lane = tid & 31, wid = tid >> 5;
    const int q0 = blockIdx.x * 128;
    const int h = blockIdx.y;
    const int kvo = (h >> 2) * DKH;
    const int r8 = lane & 7, grp = lane >> 3;

    // ---- load Q tile (128x64 fp16) into stage0 area, ldmatrix to regs
    for (int i = 0; i < 4; i++) {
        int idx = i * 256 + tid;           // 0..1023
        int row = idx >> 3, ch = idx & 7;
        uint4 v = *reinterpret_cast<const uint4*>(
            Qh + (long)(q0 + row) * D_MODEL + h * DKH + ch * 8);
        *reinterpret_cast<uint4*>(sm + SWZ(row * 128 + ch * 16)) = v;
    }
    __syncthreads();

    uint32_t qf[4][4];
    {
        int arow = wid * 16 + ((grp & 1) ? 8 : 0) + r8;
#pragma unroll
        for (int s = 0; s < 4; s++) {
            int ach = 2 * s + (grp >> 1);
            ldsm_x4(qf[s], sb + SWZ(arow * 128 + ach * 16));
        }
    }
    __syncthreads();

    const __half* kvsrc[2] = { Kh, Vh };
    auto load_kv = [&](int st, int j0n) {
        uint32_t base = sb + st * ASTAGE;
#pragma unroll
        for (int i = 0; i < 4; i++) {
            int c = i * 256 + tid;         // 0..1023
            int tsr = c >> 9;              // 0:K 1:V
            int idx = c & 511;
            int row = idx >> 3, ch = idx & 7;
            cp16(base + tsr * 8192 + SWZ(row * 128 + ch * 16),
                 kvsrc[tsr] + (long)(j0n + row) * DKV + kvo + ch * 8);
        }
        if (tid < 16) cp16(base + AMASKO + tid * 16, maskG + j0n + tid * 4);
    };

    float O[8][4];
#pragma unroll
    for (int a = 0; a < 8; a++)
#pragma unroll
        for (int c = 0; c < 4; c++) O[a][c] = 0.f;
    float sum0 = 0.f, sum1 = 0.f;
    const int cq = (lane & 3) * 2;

    load_kv(0, 0);
    CP_COMMIT();

    for (int it = 0; it < 64; it++) {
        CP_WAIT0();
        __syncthreads();
        if (it + 1 < 64) load_kv((it + 1) & 1, (it + 1) * 64);
        CP_COMMIT();

        const int st = it & 1;
        uint32_t kH = sb + st * ASTAGE, vH = kH + 8192;
        const int* maskS = reinterpret_cast<const int*>(sm + st * ASTAGE + AMASKO);

        // Two independent 32-kv halves: keeps S (16) + P (8) live instead of 32+16.
#pragma unroll
        for (int h32 = 0; h32 < 2; h32++) {
            // ---- S = Q @ K[h32*32 : +32]^T
            float S[4][4];
#pragma unroll
            for (int a = 0; a < 4; a++)
#pragma unroll
                for (int c = 0; c < 4; c++) S[a][c] = 0.f;

            {
                int broff = h32 * 32 + ((grp >= 2) ? 8 : 0) + r8;
#pragma unroll
                for (int s = 0; s < 4; s++) {
                    int bch = 2 * s + (grp & 1);
                    uint32_t bh[2][4];
#pragma unroll
                    for (int t = 0; t < 2; t++)
                        ldsm_x4(bh[t], kH + SWZ((t * 16 + broff) * 128 + bch * 16));
#pragma unroll
                    for (int nt = 0; nt < 4; nt++)
                        mma16816(S[nt], qf[s], &bh[nt >> 1][(nt & 1) * 2]);
                }
            }

            // ---- softmax (max-free; scores bounded), P in fp16 regs
            uint32_t P[8];
#pragma unroll
            for (int nt = 0; nt < 4; nt++) {
                int j = h32 * 32 + nt * 8 + cq;
                float m0 = maskS[j] ? 0.f : 1.f;
                float m1 = maskS[j + 1] ? 0.f : 1.f;
                float p0 = fexp(S[nt][0], m0);
                float p1 = fexp(S[nt][1], m1);
                float p2 = fexp(S[nt][2], m0);
                float p3 = fexp(S[nt][3], m1);
                sum0 += p0 + p1;
                sum1 += p2 + p3;
                P[nt * 2]     = packh2(p0, p1);
                P[nt * 2 + 1] = packh2(p2, p3);
            }

            // ---- O += P @ V[h32*32 : +32, :]
            {
                int vro = ((grp & 1) ? 8 : 0) + r8;
#pragma unroll
                for (int kk = 0; kk < 2; kk++) {
                    uint32_t bv[4][4];
#pragma unroll
                    for (int t = 0; t < 4; t++) {
                        int vch = 2 * t + (grp >> 1);
                        ldsm_x4_t(bv[t], vH + SWZ(((h32 * 2 + kk) * 16 + vro) * 128 + vch * 16));
                    }
                    const uint32_t* a = &P[4 * kk];
#pragma unroll
                    for (int dt = 0; dt < 8; dt++)
                        mma16816(O[dt], a, &bv[dt >> 1][(dt & 1) * 2]);
                }
            }
        }
        __syncthreads();
    }

    // ---- reduce row sums across the quad, divide, write fp16 AO
    sum0 += __shfl_xor_sync(0xffffffffu, sum0, 1);
    sum0 += __shfl_xor_sync(0xffffffffu, sum0, 2);
    sum1 += __shfl_xor_sync(0xffffffffu, sum1, 1);
    sum1 += __shfl_xor_sync(0xffffffffu, sum1, 2);
    float inv0 = 1.0f / sum0, inv1 = 1.0f / sum1;

    long row0 = q0 + wid * 16 + (lane >> 2);
#pragma unroll
    for (int dt = 0; dt < 8; dt++) {
        int col = h * DKH + dt * 8 + cq;
        *reinterpret_cast<uint32_t*>(AOh + row0 * D_MODEL + col) =
            packh2(O[dt][0] * inv0, O[dt][1] * inv0);
        *reinterpret_cast<uint32_t*>(AOh + (row0 + 8) * D_MODEL + col) =
            packh2(O[dt][2] * inv1, O[dt][3] * inv1);
    }
}

// ===========================================================================
extern "C" void kernel_launch(void* const* d_in, const int* in_sizes, int n_in,
                              void* d_out, int out_size)
{
    (void)in_sizes; (void)n_in; (void)out_size;
    const float* x  = (const float*)d_in[0];
    const int* mask = (const int*)d_in[1];
    const float* Wq = (const float*)d_in[2];
    const float* bq = (const float*)d_in[3];
    const float* Wk = (const float*)d_in[4];
    const float* bk = (const float*)d_in[5];
    const float* Wv = (const float*)d_in[6];
    const float* bv = (const float*)d_in[7];
    const float* Wo = (const float*)d_in[8];
    const float* bo = (const float*)d_in[9];
    float* out = (float*)d_out;

    __half *xh, *qh, *kh, *vh, *aoh;
    cudaGetSymbolAddress((void**)&xh, g_xh);
    cudaGetSymbolAddress((void**)&qh, g_Qh);
    cudaGetSymbolAddress((void**)&kh, g_Kh);
    cudaGetSymbolAddress((void**)&vh, g_Vh);
    cudaGetSymbolAddress((void**)&aoh, g_AOh);

    cudaFuncSetAttribute(qkv_gemm, cudaFuncAttributeMaxDynamicSharedMemorySize, GSMEM);
    cudaFuncSetAttribute(o_gemm, cudaFuncAttributeMaxDynamicSharedMemorySize, GSMEM);
    cudaFuncSetAttribute(attn_tc_kernel, cudaFuncAttributeMaxDynamicSharedMemorySize, ASMEM);

    // 1) prep
    tofp16_kernel<<<(S_LEN * D_MODEL / 4 + 255) / 256, 256>>>(x, xh, S_LEN * D_MODEL / 4);
    prep_weights_kernel<<<2560, dim3(32, 8)>>>(Wq, Wk, Wv, Wo);

    // 2) fused QKV projection (single-pass fp16 weights)
    qkv_gemm<<<dim3(12, S_LEN / 128), 256, GSMEM>>>(xh, bq, bk, bv);

    // 3) attention
    attn_tc_kernel<<<dim3(S_LEN / 128, NH), 256, ASMEM>>>(qh, kh, vh, mask, aoh);

    // 4) output projection -> fp32
    o_gemm<<<dim3(D_MODEL / 128, S_LEN / 128), 256, GSMEM>>>(aoh, bo, out);
}